// round 11
// baseline (speedup 1.0000x reference)
#include <cuda_runtime.h>

#define B_ 8
#define C_ 3
#define T_ 32
#define H_ 256
#define W_ 256
#define NB 8
#define HB (H_ / NB)
#define WB (W_ / NB)
#define BLOCKS_PER_FRAME (HB * WB)   // 1024
#define TPB 64
#define CTAS_PER_FRAME (BLOCKS_PER_FRAME / TPB)  // 16

// 2*cos(k*pi/16)
#define A1 1.96157056080646f
#define A2 1.84775906502257f
#define A3 1.66293922460509f
#define A4 1.41421356237310f
#define A5 1.11114046603920f
#define A6 0.76536686473018f
#define A7 0.39018064403226f

// Unnormalized DCT-II, 8 points, even/odd butterfly.
__device__ __forceinline__ void dct8(const float i0, const float i1, const float i2,
                                     const float i3, const float i4, const float i5,
                                     const float i6, const float i7, float o[8]) {
    float s0 = i0 + i7, s1 = i1 + i6, s2 = i2 + i5, s3 = i3 + i4;
    float d0 = i0 - i7, d1 = i1 - i6, d2 = i2 - i5, d3 = i3 - i4;
    o[0] = 2.0f * ((s0 + s3) + (s1 + s2));
    o[4] = A4 * ((s0 + s3) - (s1 + s2));
    o[2] = A2 * s0 + A6 * s1 - A6 * s2 - A2 * s3;
    o[6] = A6 * s0 - A2 * s1 + A2 * s2 - A6 * s3;
    o[1] = A1 * d0 + A3 * d1 + A5 * d2 + A7 * d3;
    o[3] = A3 * d0 - A7 * d1 - A1 * d2 - A5 * d3;
    o[5] = A5 * d0 - A1 * d1 + A7 * d2 + A3 * d3;
    o[7] = A7 * d0 - A5 * d1 + A3 * d2 - A1 * d3;
}

// 256-bit global load (sm_100+): one full 32B row-channel span per thread.
__device__ __forceinline__ void ldg256(const float* p, float r[8]) {
    asm volatile("ld.global.nc.v8.f32 {%0,%1,%2,%3,%4,%5,%6,%7}, [%8];"
        : "=f"(r[0]), "=f"(r[1]), "=f"(r[2]), "=f"(r[3]),
          "=f"(r[4]), "=f"(r[5]), "=f"(r[6]), "=f"(r[7])
        : "l"(p));
}

// 256-bit global store (sm_100+).
__device__ __forceinline__ void stg256(float* p, const float r[8]) {
    asm volatile("st.global.v8.f32 [%0], {%1,%2,%3,%4,%5,%6,%7,%8};"
        :: "l"(p),
           "f"(r[0]), "f"(r[1]), "f"(r[2]), "f"(r[3]),
           "f"(r[4]), "f"(r[5]), "f"(r[6]), "f"(r[7])
        : "memory");
}

struct Row3x8 { float a[8], g[8], c[8]; };

__device__ __forceinline__ Row3x8 load_row(const float* base0, const float* base1,
                                           const float* base2, int ro) {
    Row3x8 v;
    ldg256(base0 + ro, v.a);
    ldg256(base1 + ro, v.g);
    ldg256(base2 + ro, v.c);
    return v;
}

__device__ __forceinline__ void gray_dct_row(const Row3x8& v, float o[8]) {
    const float w0 = 0.2989f, w1 = 0.587f, w2 = 0.114f;
    float p0 = w0 * v.a[0] + w1 * v.g[0] + w2 * v.c[0];
    float p1 = w0 * v.a[1] + w1 * v.g[1] + w2 * v.c[1];
    float p2 = w0 * v.a[2] + w1 * v.g[2] + w2 * v.c[2];
    float p3 = w0 * v.a[3] + w1 * v.g[3] + w2 * v.c[3];
    float p4 = w0 * v.a[4] + w1 * v.g[4] + w2 * v.c[4];
    float p5 = w0 * v.a[5] + w1 * v.g[5] + w2 * v.c[5];
    float p6 = w0 * v.a[6] + w1 * v.g[6] + w2 * v.c[6];
    float p7 = w0 * v.a[7] + w1 * v.g[7] + w2 * v.c[7];
    dct8(p0, p1, p2, p3, p4, p5, p6, p7, o);
}

__global__ __launch_bounds__(TPB)
void dct8x8_kernel(const float* __restrict__ x, float* __restrict__ out) {
    // 16B granules; XOR swizzle keeps STS.128 and LDS.128 conflict-free.
    __shared__ float4 stage[TPB * 16];   // 16 KB

    const int tid  = threadIdx.x;
    const int lane = tid & 31;
    const int warp = tid >> 5;
    const int cta_in_frame = blockIdx.x & (CTAS_PER_FRAME - 1);
    const int frame = blockIdx.x / CTAS_PER_FRAME;    // b*T + t
    const int b = frame >> 5;
    const int t = frame & 31;

    const int p  = cta_in_frame * TPB + tid;          // block index in frame
    const int hb = p >> 5;
    const int wb = p & 31;

    const long long chan_stride = (long long)T_ * H_ * W_;
    const float* base0 = x
        + (long long)b * C_ * chan_stride
        + (long long)t * H_ * W_
        + (long long)(hb * NB) * W_
        + (long long)(wb * NB);
    const float* base1 = base0 + chan_stride;
    const float* base2 = base1 + chan_stride;

    // Software pipeline, prefetch distance 2.
    float Y[8][8];
    Row3x8 buf0 = load_row(base0, base1, base2, 0);
    Row3x8 buf1 = load_row(base0, base1, base2, W_);
    #pragma unroll
    for (int r = 0; r < 8; ++r) {
        Row3x8 nxt;
        if (r < 6) nxt = load_row(base0, base1, base2, (r + 2) * W_);
        gray_dct_row(buf0, Y[r]);
        buf0 = buf1;
        if (r < 6) buf1 = nxt;
    }

    // Stage 2: column DCT
    float Z[8][8];
    #pragma unroll
    for (int l = 0; l < 8; ++l) {
        float col[8];
        dct8(Y[0][l], Y[1][l], Y[2][l], Y[3][l],
             Y[4][l], Y[5][l], Y[6][l], Y[7][l], col);
        #pragma unroll
        for (int k = 0; k < 8; ++k) Z[k][l] = col[k];
    }

    // Stage results into smem (swizzled), 16 granules of 16B per thread.
    const float4* zsrc = (const float4*)&Z[0][0];
    #pragma unroll
    for (int i = 0; i < 16; ++i) {
        stage[tid * 16 + (i ^ (tid & 15))] = zsrc[i];
    }
    __syncwarp();

    // Coalesced 256-bit stores: each warp writes 1KB contiguous per iteration.
    float* outp = out
        + (long long)frame * (BLOCKS_PER_FRAME * 64)
        + (long long)cta_in_frame * (TPB * 64);
    #pragma unroll
    for (int c = 0; c < 8; ++c) {
        int m32 = warp * 256 + c * 32 + lane;     // 32B-granule index within CTA
        int tp  = m32 >> 3;                       // owning thread
        int j0  = (m32 & 7) * 2;                  // first 16B granule of the pair
        float4 v0 = stage[tp * 16 + ((j0    ) ^ (tp & 15))];
        float4 v1 = stage[tp * 16 + ((j0 + 1) ^ (tp & 15))];
        float r[8] = {v0.x, v0.y, v0.z, v0.w, v1.x, v1.y, v1.z, v1.w};
        stg256(outp + (long long)m32 * 8, r);
    }
}

extern "C" void kernel_launch(void* const* d_in, const int* in_sizes, int n_in,
                              void* d_out, int out_size) {
    const float* x = (const float*)d_in[0];
    float* out = (float*)d_out;
    const int grid = B_ * T_ * CTAS_PER_FRAME;  // 4096
    dct8x8_kernel<<<grid, TPB>>>(x, out);
}

// round 12
// speedup vs baseline: 1.0513x; 1.0513x over previous
#include <cuda_runtime.h>

#define B_ 8
#define C_ 3
#define T_ 32
#define H_ 256
#define W_ 256
#define NB 8
#define HB (H_ / NB)
#define WB (W_ / NB)
#define BLOCKS_PER_FRAME (HB * WB)   // 1024
#define TPB 64
#define CTAS_PER_FRAME (BLOCKS_PER_FRAME / TPB)  // 16

// 2*cos(k*pi/16)
#define A1 1.96157056080646f
#define A2 1.84775906502257f
#define A3 1.66293922460509f
#define A4 1.41421356237310f
#define A5 1.11114046603920f
#define A6 0.76536686473018f
#define A7 0.39018064403226f

// Unnormalized DCT-II, 8 points, even/odd butterfly.
__device__ __forceinline__ void dct8(const float i0, const float i1, const float i2,
                                     const float i3, const float i4, const float i5,
                                     const float i6, const float i7, float o[8]) {
    float s0 = i0 + i7, s1 = i1 + i6, s2 = i2 + i5, s3 = i3 + i4;
    float d0 = i0 - i7, d1 = i1 - i6, d2 = i2 - i5, d3 = i3 - i4;
    o[0] = 2.0f * ((s0 + s3) + (s1 + s2));
    o[4] = A4 * ((s0 + s3) - (s1 + s2));
    o[2] = A2 * s0 + A6 * s1 - A6 * s2 - A2 * s3;
    o[6] = A6 * s0 - A2 * s1 + A2 * s2 - A6 * s3;
    o[1] = A1 * d0 + A3 * d1 + A5 * d2 + A7 * d3;
    o[3] = A3 * d0 - A7 * d1 - A1 * d2 - A5 * d3;
    o[5] = A5 * d0 - A1 * d1 + A7 * d2 + A3 * d3;
    o[7] = A7 * d0 - A5 * d1 + A3 * d2 - A1 * d3;
}

// Gray row accumulator: loads issue up-front, channels folded in arrival order.
// Peak live landing regs per row: 16 (2 float4) + 8 accumulator, vs 24 before.
struct GrayRow {
    float4 r0, r1;     // pending channel pair
    float acc[8];      // gray accumulator
};

__device__ __forceinline__ void gray_row_begin(GrayRow& gr, const float* base0,
                                               const float* base1, int ro, float w0) {
    float4 a0 = __ldcs((const float4*)(base0 + ro));
    float4 a1 = __ldcs((const float4*)(base0 + ro + 4));
    gr.r0 = __ldcs((const float4*)(base1 + ro));
    gr.r1 = __ldcs((const float4*)(base1 + ro + 4));
    gr.acc[0] = w0 * a0.x; gr.acc[1] = w0 * a0.y;
    gr.acc[2] = w0 * a0.z; gr.acc[3] = w0 * a0.w;
    gr.acc[4] = w0 * a1.x; gr.acc[5] = w0 * a1.y;
    gr.acc[6] = w0 * a1.z; gr.acc[7] = w0 * a1.w;
}

__device__ __forceinline__ void gray_row_step(GrayRow& gr, const float* basen,
                                              int ro, float w, bool more) {
    float4 n0, n1;
    if (more) {
        n0 = __ldcs((const float4*)(basen + ro));
        n1 = __ldcs((const float4*)(basen + ro + 4));
    }
    gr.acc[0] += w * gr.r0.x; gr.acc[1] += w * gr.r0.y;
    gr.acc[2] += w * gr.r0.z; gr.acc[3] += w * gr.r0.w;
    gr.acc[4] += w * gr.r1.x; gr.acc[5] += w * gr.r1.y;
    gr.acc[6] += w * gr.r1.z; gr.acc[7] += w * gr.r1.w;
    if (more) { gr.r0 = n0; gr.r1 = n1; }
}

__global__ __launch_bounds__(TPB)
void dct8x8_kernel(const float* __restrict__ x, float* __restrict__ out) {
    // 16B granules; XOR swizzle keeps STS.128 and LDS.128 conflict-free.
    __shared__ float4 stage[TPB * 16];   // 16 KB

    const int tid  = threadIdx.x;
    const int lane = tid & 31;
    const int warp = tid >> 5;
    const int cta_in_frame = blockIdx.x & (CTAS_PER_FRAME - 1);
    const int frame = blockIdx.x / CTAS_PER_FRAME;    // b*T + t
    const int b = frame >> 5;
    const int t = frame & 31;

    const int p  = cta_in_frame * TPB + tid;          // block index in frame
    const int hb = p >> 5;
    const int wb = p & 31;

    const long long chan_stride = (long long)T_ * H_ * W_;
    const float* base0 = x
        + (long long)b * C_ * chan_stride
        + (long long)t * H_ * W_
        + (long long)(hb * NB) * W_
        + (long long)(wb * NB);
    const float* base1 = base0 + chan_stride;
    const float* base2 = base1 + chan_stride;

    const float w0 = 0.2989f, w1 = 0.587f, w2 = 0.114f;

    // Software pipeline over rows, prefetch distance 2, channel-accumulating.
    float Y[8][8];
    GrayRow gA, gB;
    gray_row_begin(gA, base0, base1, 0, w0);
    gray_row_begin(gB, base0, base1, W_, w0);
    #pragma unroll
    for (int r = 0; r < 8; ++r) {
        const int ro = r * W_;
        // fold ch1 into row r's acc, load ch2 for row r
        gray_row_step(gA, base2, ro, w1, true);
        // start row r+2 (ch0+ch1 loads) while row r's ch2 is in flight
        GrayRow gN;
        if (r < 6) gray_row_begin(gN, base0, base1, (r + 2) * W_, w0);
        // fold ch2, finish row r
        gray_row_step(gA, base2, 0, w2, false);
        dct8(gA.acc[0], gA.acc[1], gA.acc[2], gA.acc[3],
             gA.acc[4], gA.acc[5], gA.acc[6], gA.acc[7], Y[r]);
        gA = gB;
        if (r < 6) gB = gN;
    }

    // Stage 2: column DCT
    float Z[8][8];
    #pragma unroll
    for (int l = 0; l < 8; ++l) {
        float col[8];
        dct8(Y[0][l], Y[1][l], Y[2][l], Y[3][l],
             Y[4][l], Y[5][l], Y[6][l], Y[7][l], col);
        #pragma unroll
        for (int k = 0; k < 8; ++k) Z[k][l] = col[k];
    }

    // Stage results into smem (swizzled), 16 granules of 16B per thread.
    const float4* zsrc = (const float4*)&Z[0][0];
    #pragma unroll
    for (int i = 0; i < 16; ++i) {
        stage[tid * 16 + (i ^ (tid & 15))] = zsrc[i];
    }
    __syncwarp();

    // Coalesced store: each warp writes its own 32 threads' 8KB contiguously.
    float4* out4 = (float4*)out
        + (long long)frame * (BLOCKS_PER_FRAME * 16)
        + (long long)cta_in_frame * (TPB * 16);
    #pragma unroll
    for (int c = 0; c < 16; ++c) {
        int m  = warp * 512 + c * 32 + lane;   // linear granule within CTA
        int tp = m >> 4;
        int j  = m & 15;
        float4 v = stage[tp * 16 + (j ^ (tp & 15))];
        __stcs(&out4[m], v);
    }
}

extern "C" void kernel_launch(void* const* d_in, const int* in_sizes, int n_in,
                              void* d_out, int out_size) {
    const float* x = (const float*)d_in[0];
    float* out = (float*)d_out;
    const int grid = B_ * T_ * CTAS_PER_FRAME;  // 4096
    dct8x8_kernel<<<grid, TPB>>>(x, out);
}